// round 7
// baseline (speedup 1.0000x reference)
#include <cuda_runtime.h>
#include <cuda_bf16.h>

#define NN 50000
#define EE 800000
#define IC  128
#define OC  64
#define SCAN_B 512
#define NB ((NN + SCAN_B - 1) / SCAN_B)   // 98 scan blocks

// ---- scratch (no device allocations; zero-initialized at module load) ----
__device__ __align__(16) float g_h[NN * OC];   // projected features
__device__ float g_adst[NN];                   // dot(h[n], att[0:64])
__device__ float g_asrc[NN];                   // dot(h[n], att[64:128])
__device__ int   g_deg[NN];                    // in-degree (zeros on entry; restored by scan)
__device__ int   g_ptr[NN + 1];                // CSR row pointers (by dst)
__device__ int   g_cursor[NN];                 // fill cursors
__device__ int   g_col[EE];                    // CSR: src per slot
__device__ int   g_agg[128];                   // scan block aggregates
__device__ int   g_flag[128];                  // publish flags (zeros on entry; reset by k5)

// int64-layout sniff: ids < 2^31 => odd 32-bit words all zero
__device__ __forceinline__ bool sniff64(const int* ei32) {
    int z = (ei32[1] == 0) + (ei32[3] == 0) + (ei32[5] == 0) +
            (ei32[7] == 0) + (ei32[9] == 0) + (ei32[11] == 0);
    return z == 6;
}

// ============================================================
// K0: in-degree histogram straight from edge_index (dst half).
// g_deg is guaranteed zero on entry (load-time zero-init for the
// first run; k2_scan restores zeros on every run).
// ============================================================
__global__ void k0_hist(const int* __restrict__ ei32) {
    int e = blockIdx.x * blockDim.x + threadIdx.x;
    if (e >= EE) return;
    bool is64 = sniff64(ei32);
    int d = is64 ? ei32[2 * (EE + e)] : ei32[EE + e];
    d = min(max(d, 0), NN - 1);
    atomicAdd(&g_deg[d], 1);
}

// ============================================================
// K1: h = x @ W (50000x128 @ 128x64 fp32) + fused attention dots
// ============================================================
__global__ void k1_gemm(const float* __restrict__ x, const float* __restrict__ W,
                        const float* __restrict__ att) {
    __shared__ float Ws[64][64];
    __shared__ float Xs[64][68];
    const int tid = threadIdx.x;
    const int tx = tid & 15;
    const int ty = tid >> 4;
    const int n0 = blockIdx.x * 64;

    float att_d[4], att_s[4];
#pragma unroll
    for (int j = 0; j < 4; j++) {
        att_d[j] = att[tx * 4 + j];
        att_s[j] = att[64 + tx * 4 + j];
    }

    float acc[4][4];
#pragma unroll
    for (int i = 0; i < 4; i++)
#pragma unroll
        for (int j = 0; j < 4; j++) acc[i][j] = 0.f;

    for (int kc = 0; kc < IC; kc += 64) {
        for (int i = tid; i < 64 * 64; i += 256) {
            int k = i >> 6, c = i & 63;
            Ws[k][c] = W[(kc + k) * OC + c];
        }
        for (int i = tid; i < 64 * 64; i += 256) {
            int r = i >> 6, k = i & 63;
            int n = n0 + r;
            Xs[k][r] = (n < NN) ? x[n * IC + kc + k] : 0.f;
        }
        __syncthreads();
#pragma unroll
        for (int k = 0; k < 64; k++) {
            float4 xv = *(const float4*)&Xs[k][ty * 4];
            float4 wv = *(const float4*)&Ws[k][tx * 4];
            float xa[4] = {xv.x, xv.y, xv.z, xv.w};
            float wa[4] = {wv.x, wv.y, wv.z, wv.w};
#pragma unroll
            for (int i = 0; i < 4; i++)
#pragma unroll
                for (int j = 0; j < 4; j++) acc[i][j] += xa[i] * wa[j];
        }
        __syncthreads();
    }

#pragma unroll
    for (int i = 0; i < 4; i++) {
        int n = n0 + ty * 4 + i;
        if (n < NN) {
            float4 v = make_float4(acc[i][0], acc[i][1], acc[i][2], acc[i][3]);
            *(float4*)(g_h + n * OC + tx * 4) = v;
        }
        float pd = acc[i][0] * att_d[0] + acc[i][1] * att_d[1] +
                   acc[i][2] * att_d[2] + acc[i][3] * att_d[3];
        float ps = acc[i][0] * att_s[0] + acc[i][1] * att_s[1] +
                   acc[i][2] * att_s[2] + acc[i][3] * att_s[3];
#pragma unroll
        for (int o = 8; o > 0; o >>= 1) {
            pd += __shfl_down_sync(0xffffffffu, pd, o, 16);
            ps += __shfl_down_sync(0xffffffffu, ps, o, 16);
        }
        if (tx == 0 && n < NN) {
            g_adst[n] = pd;
            g_asrc[n] = ps;
        }
    }
}

// ============================================================
// K2: single-launch exclusive scan deg -> ptr (98 blocks, one
// wave; lookback on published aggregates). Restores g_deg = 0.
// ============================================================
__global__ void k2_scan() {
    __shared__ int wsum[16];
    __shared__ int red[128];
    const int bid = blockIdx.x;
    const int tid = threadIdx.x;
    const int n = bid * SCAN_B + tid;
    const int lane = tid & 31, wid = tid >> 5;

    int v = (n < NN) ? g_deg[n] : 0;
    if (n < NN) g_deg[n] = 0;          // restore invariant for next run
    int s = v;
#pragma unroll
    for (int o = 1; o < 32; o <<= 1) {
        int t = __shfl_up_sync(0xffffffffu, s, o);
        if (lane >= o) s += t;
    }
    if (lane == 31) wsum[wid] = s;
    __syncthreads();
    if (wid == 0) {
        int ws = (lane < 16) ? wsum[lane] : 0;
#pragma unroll
        for (int o = 1; o < 16; o <<= 1) {
            int t = __shfl_up_sync(0xffffffffu, ws, o);
            if (lane >= o) ws += t;
        }
        if (lane < 16) wsum[lane] = ws;
    }
    __syncthreads();

    // publish this block's aggregate
    if (tid == 0) {
        g_agg[bid] = wsum[15];
        __threadfence();
        atomicExch(&g_flag[bid], 1);
    }

    // lookback: sum aggregates of blocks 0..bid-1 (all resident, one wave)
    if (tid < 128) {
        int val = 0;
        if (tid < bid) {
            while (atomicAdd(&g_flag[tid], 0) == 0) { }
            __threadfence();
            val = g_agg[tid];
        }
        red[tid] = val;
    }
    __syncthreads();
#pragma unroll
    for (int o = 64; o > 0; o >>= 1) {
        if (tid < o) red[tid] += red[tid + o];
        __syncthreads();
    }
    const int prefix = red[0];

    int excl = prefix + s - v + ((wid > 0) ? wsum[wid - 1] : 0);
    if (n < NN) {
        g_ptr[n] = excl;
        g_cursor[n] = excl;
    }
    if (n == 0) g_ptr[NN] = EE;
}

// ============================================================
// K5: fill CSR columns straight from edge_index; reset scan flags
// ============================================================
__global__ void k5_fill(const int* __restrict__ ei32) {
    int e = blockIdx.x * blockDim.x + threadIdx.x;
    if (e < 128) g_flag[e] = 0;        // reset for next run
    if (e >= EE) return;
    bool is64 = sniff64(ei32);
    int s, d;
    if (is64) {
        s = ei32[2 * e];
        d = ei32[2 * (EE + e)];
    } else {
        s = ei32[e];
        d = ei32[EE + e];
    }
    s = min(max(s, 0), NN - 1);
    d = min(max(d, 0), NN - 1);
    int pos = atomicAdd(&g_cursor[d], 1);
    g_col[pos] = s;
}

// ============================================================
// K6: fused gather + softmax + bias + L2 norm. warp/node, x4 ILP
// ============================================================
__global__ void k6_gather(const float* __restrict__ bias, float* __restrict__ out) {
    const int lane = threadIdx.x & 31;
    const int n = blockIdx.x * 8 + (threadIdx.x >> 5);
    if (n >= NN) return;

    const float ad = g_adst[n];
    const float2 bv = *(const float2*)(bias + lane * 2);

    // self loop
    float al = ad + g_asrc[n];
    al = (al > 0.f) ? al : 0.2f * al;
    float w = __expf(al);
    float2 hv = *(const float2*)(g_h + n * OC + lane * 2);
    float ws0 = w,  a0 = w * hv.x, a1 = w * hv.y;
    float ws1 = 0.f, b0 = 0.f, b1 = 0.f;
    float ws2 = 0.f, c0 = 0.f, c1 = 0.f;
    float ws3 = 0.f, d0 = 0.f, d1 = 0.f;

    const int beg = g_ptr[n];
    const int end = g_ptr[n + 1];
    int i = beg;
    for (; i + 3 < end; i += 4) {
        int s0 = g_col[i];
        int s1 = g_col[i + 1];
        int s2 = g_col[i + 2];
        int s3 = g_col[i + 3];
        float x0 = g_asrc[s0];
        float x1 = g_asrc[s1];
        float x2 = g_asrc[s2];
        float x3 = g_asrc[s3];
        float2 h0 = *(const float2*)(g_h + s0 * OC + lane * 2);
        float2 h1 = *(const float2*)(g_h + s1 * OC + lane * 2);
        float2 h2 = *(const float2*)(g_h + s2 * OC + lane * 2);
        float2 h3 = *(const float2*)(g_h + s3 * OC + lane * 2);
        float e0 = ad + x0; e0 = (e0 > 0.f) ? e0 : 0.2f * e0;
        float e1 = ad + x1; e1 = (e1 > 0.f) ? e1 : 0.2f * e1;
        float e2 = ad + x2; e2 = (e2 > 0.f) ? e2 : 0.2f * e2;
        float e3 = ad + x3; e3 = (e3 > 0.f) ? e3 : 0.2f * e3;
        float w0 = __expf(e0);
        float w1 = __expf(e1);
        float w2 = __expf(e2);
        float w3 = __expf(e3);
        ws0 += w0; a0 += w0 * h0.x; a1 += w0 * h0.y;
        ws1 += w1; b0 += w1 * h1.x; b1 += w1 * h1.y;
        ws2 += w2; c0 += w2 * h2.x; c1 += w2 * h2.y;
        ws3 += w3; d0 += w3 * h3.x; d1 += w3 * h3.y;
    }
    for (; i < end; i++) {
        int s = g_col[i];
        float a = ad + g_asrc[s];
        a = (a > 0.f) ? a : 0.2f * a;
        float we = __expf(a);
        float2 h2 = *(const float2*)(g_h + s * OC + lane * 2);
        ws0 += we; a0 += we * h2.x; a1 += we * h2.y;
    }
    float wsum = (ws0 + ws1) + (ws2 + ws3);
    a0 = (a0 + b0) + (c0 + d0);
    a1 = (a1 + b1) + (c1 + d1);

    float inv_s = 1.0f / (wsum + 1e-16f);
    float v0 = a0 * inv_s + bv.x;
    float v1 = a1 * inv_s + bv.y;

    float ss = v0 * v0 + v1 * v1;
#pragma unroll
    for (int o = 16; o > 0; o >>= 1) ss += __shfl_xor_sync(0xffffffffu, ss, o);
    float inv = 1.0f / fmaxf(sqrtf(ss), 1e-12f);
    *(float2*)(out + n * OC + lane * 2) = make_float2(v0 * inv, v1 * inv);
}

extern "C" void kernel_launch(void* const* d_in, const int* in_sizes, int n_in,
                              void* d_out, int out_size) {
    const float* x = (const float*)d_in[0];
    const int* ei32 = (const int*)d_in[1];   // dtype sniffed on device
    const float* W = (const float*)d_in[2];
    const float* att = (const float*)d_in[3];
    const float* bias = (const float*)d_in[4];
    float* out = (float*)d_out;

    k0_hist<<<(EE + 255) / 256, 256>>>(ei32);
    k1_gemm<<<(NN + 63) / 64, 256>>>(x, W, att);
    k2_scan<<<NB, SCAN_B>>>();
    k5_fill<<<(EE + 255) / 256, 256>>>(ei32);
    k6_gather<<<(NN + 7) / 8, 256>>>(bias, out);
}

// round 9
// speedup vs baseline: 1.1304x; 1.1304x over previous
#include <cuda_runtime.h>
#include <cuda_bf16.h>

#define NN 50000
#define EE 800000
#define IC  128
#define OC  64
#define TILES ((NN + 63) / 64)        // 782 gemm tiles
#define BUILD_BLOCKS 148
#define GEMM_BLOCKS  296
#define GRID (BUILD_BLOCKS + GEMM_BLOCKS)
#define SCAN_BLOCKS 98                // 98 * 512 >= NN

// ---- scratch (no device allocations; zero-initialized at module load) ----
__device__ __align__(16) float g_h[NN * OC];
__device__ float g_adst[NN];
__device__ float g_asrc[NN];
__device__ int   g_deg[NN];       // zeros on entry; restored during scan
__device__ int   g_ptr[NN + 1];
__device__ int   g_cursor[NN];
__device__ int   g_col[EE];
__device__ int   g_agg[128];
__device__ int   g_barcnt[3];     // build barrier counters (reset by k6)
__device__ int   g_barrel[3];     // build barrier release flags (reset by k6)

// int64-layout sniff: ids < 2^31 => odd 32-bit words all zero
__device__ __forceinline__ bool sniff64(const int* ei32) {
    int z = (ei32[1] == 0) + (ei32[3] == 0) + (ei32[5] == 0) +
            (ei32[7] == 0) + (ei32[9] == 0) + (ei32[11] == 0);
    return z == 6;
}

// barrier among the BUILD_BLOCKS build blocks (all resident => safe spin)
__device__ __forceinline__ void build_barrier(int id) {
    __syncthreads();
    if (threadIdx.x == 0) {
        __threadfence();
        int prev = atomicAdd(&g_barcnt[id], 1);
        if (prev == BUILD_BLOCKS - 1) {
            __threadfence();
            atomicExch(&g_barrel[id], 1);
        }
        while (atomicAdd(&g_barrel[id], 0) == 0) { }
        __threadfence();
    }
    __syncthreads();
}

// ============================================================
// MEGA: blocks [0,148) build CSR; blocks [148,444) do the GEMM
// (h = x@W + fused attention dots). Independent data => overlap.
// ============================================================
__global__ __launch_bounds__(256, 3) void mega(
    const float* __restrict__ x, const float* __restrict__ W,
    const float* __restrict__ att, const int* __restrict__ ei32)
{
    __shared__ float Ws[64][64];
    __shared__ float Xs[64][68];
    __shared__ int   ish[128];
    const int tid = threadIdx.x;
    const int bid = blockIdx.x;

    if (bid < BUILD_BLOCKS) {
        // ---------------- build role ----------------
        const bool is64 = sniff64(ei32);

        // Phase A: in-degree histogram
        for (int e = bid * 256 + tid; e < EE; e += BUILD_BLOCKS * 256) {
            int d = is64 ? ei32[2 * (EE + e)] : ei32[EE + e];
            d = min(max(d, 0), NN - 1);
            atomicAdd(&g_deg[d], 1);
        }
        build_barrier(0);

        // Phase B1: local exclusive scan (blocks 0..97, 512 elems each)
        int v0 = 0, v1 = 0, local_excl = 0;
        int i0 = 0, i1 = 0;
        if (bid < SCAN_BLOCKS) {
            const int lane = tid & 31, wid = tid >> 5;
            i0 = bid * 512 + 2 * tid;
            i1 = i0 + 1;
            v0 = (i0 < NN) ? g_deg[i0] : 0;
            v1 = (i1 < NN) ? g_deg[i1] : 0;
            if (i0 < NN) g_deg[i0] = 0;    // restore invariant
            if (i1 < NN) g_deg[i1] = 0;
            int ts = v0 + v1, s = ts;
#pragma unroll
            for (int o = 1; o < 32; o <<= 1) {
                int t = __shfl_up_sync(0xffffffffu, s, o);
                if (lane >= o) s += t;
            }
            if (lane == 31) ish[wid] = s;
            __syncthreads();
            if (wid == 0 && lane < 8) {
                int ws = ish[lane];
#pragma unroll
                for (int o = 1; o < 8; o <<= 1) {
                    int t = __shfl_up_sync(0x000000ffu, ws, o);
                    if (lane >= o) ws += t;
                }
                ish[lane] = ws;
            }
            __syncthreads();
            local_excl = (s - ts) + ((wid > 0) ? ish[wid - 1] : 0);
            // single writer publishes the block aggregate (race fixed)
            if (tid == 0) g_agg[bid] = ish[7];
            __syncthreads();
        }
        build_barrier(1);

        // Phase B2: cross-block prefix + write ptr/cursor
        if (bid < SCAN_BLOCKS) {
            if (tid < 128) ish[tid] = (tid < bid) ? g_agg[tid] : 0;
            __syncthreads();
#pragma unroll
            for (int o = 64; o > 0; o >>= 1) {
                if (tid < o) ish[tid] += ish[tid + o];
                __syncthreads();
            }
            const int prefix = ish[0];
            int e0 = prefix + local_excl;
            if (i0 < NN) { g_ptr[i0] = e0;      g_cursor[i0] = e0; }
            if (i1 < NN) { g_ptr[i1] = e0 + v0; g_cursor[i1] = e0 + v0; }
            if (bid == 0 && tid == 0) g_ptr[NN] = EE;
        }
        build_barrier(2);

        // Phase C: fill CSR columns
        for (int e = bid * 256 + tid; e < EE; e += BUILD_BLOCKS * 256) {
            int s, d;
            if (is64) { s = ei32[2 * e]; d = ei32[2 * (EE + e)]; }
            else      { s = ei32[e];     d = ei32[EE + e]; }
            s = min(max(s, 0), NN - 1);
            d = min(max(d, 0), NN - 1);
            int pos = atomicAdd(&g_cursor[d], 1);
            g_col[pos] = s;
        }
    } else {
        // ---------------- gemm role ----------------
        const int tx = tid & 15;
        const int ty = tid >> 4;

        float att_d[4], att_s[4];
#pragma unroll
        for (int j = 0; j < 4; j++) {
            att_d[j] = att[tx * 4 + j];
            att_s[j] = att[64 + tx * 4 + j];
        }

        for (int tile = bid - BUILD_BLOCKS; tile < TILES; tile += GEMM_BLOCKS) {
            const int n0 = tile * 64;
            float acc[4][4];
#pragma unroll
            for (int i = 0; i < 4; i++)
#pragma unroll
                for (int j = 0; j < 4; j++) acc[i][j] = 0.f;

            for (int kc = 0; kc < IC; kc += 64) {
                for (int i = tid; i < 64 * 64; i += 256) {
                    int k = i >> 6, c = i & 63;
                    Ws[k][c] = W[(kc + k) * OC + c];
                }
                for (int i = tid; i < 64 * 64; i += 256) {
                    int r = i >> 6, k = i & 63;
                    int n = n0 + r;
                    Xs[k][r] = (n < NN) ? x[n * IC + kc + k] : 0.f;
                }
                __syncthreads();
#pragma unroll
                for (int k = 0; k < 64; k++) {
                    float4 xv = *(const float4*)&Xs[k][ty * 4];
                    float4 wv = *(const float4*)&Ws[k][tx * 4];
                    float xa[4] = {xv.x, xv.y, xv.z, xv.w};
                    float wa[4] = {wv.x, wv.y, wv.z, wv.w};
#pragma unroll
                    for (int i = 0; i < 4; i++)
#pragma unroll
                        for (int j = 0; j < 4; j++) acc[i][j] += xa[i] * wa[j];
                }
                __syncthreads();
            }

#pragma unroll
            for (int i = 0; i < 4; i++) {
                int n = n0 + ty * 4 + i;
                if (n < NN) {
                    float4 v = make_float4(acc[i][0], acc[i][1], acc[i][2], acc[i][3]);
                    *(float4*)(g_h + n * OC + tx * 4) = v;
                }
                float pd = acc[i][0] * att_d[0] + acc[i][1] * att_d[1] +
                           acc[i][2] * att_d[2] + acc[i][3] * att_d[3];
                float ps = acc[i][0] * att_s[0] + acc[i][1] * att_s[1] +
                           acc[i][2] * att_s[2] + acc[i][3] * att_s[3];
#pragma unroll
                for (int o = 8; o > 0; o >>= 1) {
                    pd += __shfl_down_sync(0xffffffffu, pd, o, 16);
                    ps += __shfl_down_sync(0xffffffffu, ps, o, 16);
                }
                if (tx == 0 && n < NN) {
                    g_adst[n] = pd;
                    g_asrc[n] = ps;
                }
            }
        }
    }
}

// ============================================================
// K6: fused gather + softmax + bias + L2 norm. warp/node, x4 ILP.
// Also resets the mega-kernel barrier state for the next replay.
// ============================================================
__global__ void k6_gather(const float* __restrict__ bias, float* __restrict__ out) {
    if (blockIdx.x == 0 && threadIdx.x < 3) {
        g_barcnt[threadIdx.x] = 0;
        g_barrel[threadIdx.x] = 0;
    }
    const int lane = threadIdx.x & 31;
    const int n = blockIdx.x * 8 + (threadIdx.x >> 5);
    if (n >= NN) return;

    const float ad = g_adst[n];
    const float2 bv = *(const float2*)(bias + lane * 2);

    // self loop
    float al = ad + g_asrc[n];
    al = (al > 0.f) ? al : 0.2f * al;
    float w = __expf(al);
    float2 hv = *(const float2*)(g_h + n * OC + lane * 2);
    float ws0 = w,  a0 = w * hv.x, a1 = w * hv.y;
    float ws1 = 0.f, b0 = 0.f, b1 = 0.f;
    float ws2 = 0.f, c0 = 0.f, c1 = 0.f;
    float ws3 = 0.f, d0 = 0.f, d1 = 0.f;

    const int beg = g_ptr[n];
    const int end = g_ptr[n + 1];
    int i = beg;
    for (; i + 3 < end; i += 4) {
        int s0 = g_col[i];
        int s1 = g_col[i + 1];
        int s2 = g_col[i + 2];
        int s3 = g_col[i + 3];
        float x0 = g_asrc[s0];
        float x1 = g_asrc[s1];
        float x2 = g_asrc[s2];
        float x3 = g_asrc[s3];
        float2 h0 = *(const float2*)(g_h + s0 * OC + lane * 2);
        float2 h1 = *(const float2*)(g_h + s1 * OC + lane * 2);
        float2 h2 = *(const float2*)(g_h + s2 * OC + lane * 2);
        float2 h3 = *(const float2*)(g_h + s3 * OC + lane * 2);
        float e0 = ad + x0; e0 = (e0 > 0.f) ? e0 : 0.2f * e0;
        float e1 = ad + x1; e1 = (e1 > 0.f) ? e1 : 0.2f * e1;
        float e2 = ad + x2; e2 = (e2 > 0.f) ? e2 : 0.2f * e2;
        float e3 = ad + x3; e3 = (e3 > 0.f) ? e3 : 0.2f * e3;
        float w0 = __expf(e0);
        float w1 = __expf(e1);
        float w2 = __expf(e2);
        float w3 = __expf(e3);
        ws0 += w0; a0 += w0 * h0.x; a1 += w0 * h0.y;
        ws1 += w1; b0 += w1 * h1.x; b1 += w1 * h1.y;
        ws2 += w2; c0 += w2 * h2.x; c1 += w2 * h2.y;
        ws3 += w3; d0 += w3 * h3.x; d1 += w3 * h3.y;
    }
    for (; i < end; i++) {
        int s = g_col[i];
        float a = ad + g_asrc[s];
        a = (a > 0.f) ? a : 0.2f * a;
        float we = __expf(a);
        float2 h2 = *(const float2*)(g_h + s * OC + lane * 2);
        ws0 += we; a0 += we * h2.x; a1 += we * h2.y;
    }
    float wsum = (ws0 + ws1) + (ws2 + ws3);
    a0 = (a0 + b0) + (c0 + d0);
    a1 = (a1 + b1) + (c1 + d1);

    float inv_s = 1.0f / (wsum + 1e-16f);
    float v0 = a0 * inv_s + bv.x;
    float v1 = a1 * inv_s + bv.y;

    float ss = v0 * v0 + v1 * v1;
#pragma unroll
    for (int o = 16; o > 0; o >>= 1) ss += __shfl_xor_sync(0xffffffffu, ss, o);
    float inv = 1.0f / fmaxf(sqrtf(ss), 1e-12f);
    *(float2*)(out + n * OC + lane * 2) = make_float2(v0 * inv, v1 * inv);
}

extern "C" void kernel_launch(void* const* d_in, const int* in_sizes, int n_in,
                              void* d_out, int out_size) {
    const float* x = (const float*)d_in[0];
    const int* ei32 = (const int*)d_in[1];   // dtype sniffed on device
    const float* W = (const float*)d_in[2];
    const float* att = (const float*)d_in[3];
    const float* bias = (const float*)d_in[4];
    float* out = (float*)d_out;

    mega<<<GRID, 256>>>(x, W, att, ei32);
    k6_gather<<<(NN + 7) / 8, 256>>>(bias, out);
}

// round 10
// speedup vs baseline: 1.1796x; 1.0436x over previous
#include <cuda_runtime.h>
#include <cuda_bf16.h>

#define NN 50000
#define EE 800000
#define IC  128
#define OC  64
#define TILES ((NN + 63) / 64)        // 782 gemm tiles
#define BUILD_BLOCKS 112
#define GEMM_BLOCKS  332
#define GRID (BUILD_BLOCKS + GEMM_BLOCKS)   // 444 = 148 SM * 3 -> one wave
#define SCAN_BLOCKS 98                // 98 * 512 >= NN

// ---- scratch (no device allocations; zero-initialized at module load) ----
__device__ __align__(16) float g_h[NN * OC];
__device__ float g_adst[NN];
__device__ float g_asrc[NN];
__device__ int   g_deg[NN];       // zeros on entry; restored during scan
__device__ int   g_ptr[NN + 1];
__device__ int   g_cursor[NN];
__device__ int   g_col[EE];
__device__ int   g_agg[128];
__device__ int   g_barcnt[3];     // build barrier counters (reset by k6)
__device__ int   g_barrel[3];     // build barrier release flags (reset by k6)

// int64-layout sniff: ids < 2^31 => odd 32-bit words all zero
__device__ __forceinline__ bool sniff64(const int* ei32) {
    int z = (ei32[1] == 0) + (ei32[3] == 0) + (ei32[5] == 0) +
            (ei32[7] == 0) + (ei32[9] == 0) + (ei32[11] == 0);
    return z == 6;
}

// barrier among the BUILD_BLOCKS build blocks (all resident => safe spin)
__device__ __forceinline__ void build_barrier(int id) {
    __syncthreads();
    if (threadIdx.x == 0) {
        __threadfence();
        int prev = atomicAdd(&g_barcnt[id], 1);
        if (prev == BUILD_BLOCKS - 1) {
            __threadfence();
            atomicExch(&g_barrel[id], 1);
        }
        while (atomicAdd(&g_barrel[id], 0) == 0) { }
        __threadfence();
    }
    __syncthreads();
}

// packed fp32x2 FMA: d = a * b + d  (sm_100+)
__device__ __forceinline__ void ffma2(unsigned long long& d,
                                      unsigned long long a,
                                      unsigned long long b) {
    asm("fma.rn.f32x2 %0, %1, %2, %0;" : "+l"(d) : "l"(a), "l"(b));
}
__device__ __forceinline__ unsigned long long dup2(float v) {
    unsigned long long p;
    unsigned int b = __float_as_uint(v);
    asm("mov.b64 %0, {%1, %2};" : "=l"(p) : "r"(b), "r"(b));
    return p;
}
__device__ __forceinline__ float2 unpack2(unsigned long long p) {
    unsigned int lo, hi;
    asm("mov.b64 {%0, %1}, %2;" : "=r"(lo), "=r"(hi) : "l"(p));
    return make_float2(__uint_as_float(lo), __uint_as_float(hi));
}

// ============================================================
// MEGA: blocks [0,112) build CSR; blocks [112,444) do the GEMM
// (h = x@W + fused attention dots), f32x2-packed FMAs.
// ============================================================
__global__ __launch_bounds__(256, 3) void mega(
    const float* __restrict__ x, const float* __restrict__ W,
    const float* __restrict__ att, const int* __restrict__ ei32)
{
    __shared__ float Ws[64][64];
    __shared__ float Xs[64][68];
    __shared__ int   ish[128];
    const int tid = threadIdx.x;
    const int bid = blockIdx.x;

    if (bid < BUILD_BLOCKS) {
        // ---------------- build role ----------------
        const bool is64 = sniff64(ei32);

        // Phase A: in-degree histogram
        for (int e = bid * 256 + tid; e < EE; e += BUILD_BLOCKS * 256) {
            int d = is64 ? ei32[2 * (EE + e)] : ei32[EE + e];
            d = min(max(d, 0), NN - 1);
            atomicAdd(&g_deg[d], 1);
        }
        build_barrier(0);

        // Phase B1: local exclusive scan (blocks 0..97, 512 elems each)
        int v0 = 0, v1 = 0, local_excl = 0;
        int i0 = 0, i1 = 0;
        if (bid < SCAN_BLOCKS) {
            const int lane = tid & 31, wid = tid >> 5;
            i0 = bid * 512 + 2 * tid;
            i1 = i0 + 1;
            v0 = (i0 < NN) ? g_deg[i0] : 0;
            v1 = (i1 < NN) ? g_deg[i1] : 0;
            if (i0 < NN) g_deg[i0] = 0;    // restore invariant
            if (i1 < NN) g_deg[i1] = 0;
            int ts = v0 + v1, s = ts;
#pragma unroll
            for (int o = 1; o < 32; o <<= 1) {
                int t = __shfl_up_sync(0xffffffffu, s, o);
                if (lane >= o) s += t;
            }
            if (lane == 31) ish[wid] = s;
            __syncthreads();
            if (wid == 0 && lane < 8) {
                int ws = ish[lane];
#pragma unroll
                for (int o = 1; o < 8; o <<= 1) {
                    int t = __shfl_up_sync(0x000000ffu, ws, o);
                    if (lane >= o) ws += t;
                }
                ish[lane] = ws;
            }
            __syncthreads();
            local_excl = (s - ts) + ((wid > 0) ? ish[wid - 1] : 0);
            if (tid == 0) g_agg[bid] = ish[7];   // single writer
            __syncthreads();
        }
        build_barrier(1);

        // Phase B2: cross-block prefix + write ptr/cursor
        if (bid < SCAN_BLOCKS) {
            if (tid < 128) ish[tid] = (tid < bid) ? g_agg[tid] : 0;
            __syncthreads();
#pragma unroll
            for (int o = 64; o > 0; o >>= 1) {
                if (tid < o) ish[tid] += ish[tid + o];
                __syncthreads();
            }
            const int prefix = ish[0];
            int e0 = prefix + local_excl;
            if (i0 < NN) { g_ptr[i0] = e0;      g_cursor[i0] = e0; }
            if (i1 < NN) { g_ptr[i1] = e0 + v0; g_cursor[i1] = e0 + v0; }
            if (bid == 0 && tid == 0) g_ptr[NN] = EE;
        }
        build_barrier(2);

        // Phase C: fill CSR columns
        for (int e = bid * 256 + tid; e < EE; e += BUILD_BLOCKS * 256) {
            int s, d;
            if (is64) { s = ei32[2 * e]; d = ei32[2 * (EE + e)]; }
            else      { s = ei32[e];     d = ei32[EE + e]; }
            s = min(max(s, 0), NN - 1);
            d = min(max(d, 0), NN - 1);
            int pos = atomicAdd(&g_cursor[d], 1);
            g_col[pos] = s;
        }
    } else {
        // ---------------- gemm role ----------------
        const int tx = tid & 15;
        const int ty = tid >> 4;

        float att_d[4], att_s[4];
#pragma unroll
        for (int j = 0; j < 4; j++) {
            att_d[j] = att[tx * 4 + j];
            att_s[j] = att[64 + tx * 4 + j];
        }

        for (int tile = bid - BUILD_BLOCKS; tile < TILES; tile += GEMM_BLOCKS) {
            const int n0 = tile * 64;
            // acc packed over column pairs: accp[i][p] = cols (tx*4+2p, tx*4+2p+1)
            unsigned long long accp[4][2];
#pragma unroll
            for (int i = 0; i < 4; i++) { accp[i][0] = 0ull; accp[i][1] = 0ull; }

            for (int kc = 0; kc < IC; kc += 64) {
                for (int i = tid; i < 64 * 64; i += 256) {
                    int k = i >> 6, c = i & 63;
                    Ws[k][c] = W[(kc + k) * OC + c];
                }
                for (int i = tid; i < 64 * 64; i += 256) {
                    int r = i >> 6, k = i & 63;
                    int n = n0 + r;
                    Xs[k][r] = (n < NN) ? x[n * IC + kc + k] : 0.f;
                }
                __syncthreads();
#pragma unroll
                for (int k = 0; k < 64; k++) {
                    float4 xv = *(const float4*)&Xs[k][ty * 4];
                    const unsigned long long* wp =
                        (const unsigned long long*)&Ws[k][tx * 4];
                    unsigned long long w0 = wp[0], w1 = wp[1];
                    unsigned long long x0 = dup2(xv.x);
                    unsigned long long x1 = dup2(xv.y);
                    unsigned long long x2 = dup2(xv.z);
                    unsigned long long x3 = dup2(xv.w);
                    ffma2(accp[0][0], x0, w0); ffma2(accp[0][1], x0, w1);
                    ffma2(accp[1][0], x1, w0); ffma2(accp[1][1], x1, w1);
                    ffma2(accp[2][0], x2, w0); ffma2(accp[2][1], x2, w1);
                    ffma2(accp[3][0], x3, w0); ffma2(accp[3][1], x3, w1);
                }
                __syncthreads();
            }

#pragma unroll
            for (int i = 0; i < 4; i++) {
                float2 p0 = unpack2(accp[i][0]);
                float2 p1 = unpack2(accp[i][1]);
                int n = n0 + ty * 4 + i;
                if (n < NN) {
                    float4 v = make_float4(p0.x, p0.y, p1.x, p1.y);
                    *(float4*)(g_h + n * OC + tx * 4) = v;
                }
                float pd = p0.x * att_d[0] + p0.y * att_d[1] +
                           p1.x * att_d[2] + p1.y * att_d[3];
                float ps = p0.x * att_s[0] + p0.y * att_s[1] +
                           p1.x * att_s[2] + p1.y * att_s[3];
#pragma unroll
                for (int o = 8; o > 0; o >>= 1) {
                    pd += __shfl_down_sync(0xffffffffu, pd, o, 16);
                    ps += __shfl_down_sync(0xffffffffu, ps, o, 16);
                }
                if (tx == 0 && n < NN) {
                    g_adst[n] = pd;
                    g_asrc[n] = ps;
                }
            }
        }
    }
}

// ============================================================
// K6: fused gather + softmax + bias + L2 norm. warp/node.
// Edge weights computed once per edge (lane-distributed), then
// shfl-broadcast; only the h-FMA uses all 32 lanes.
// ============================================================
__global__ void k6_gather(const float* __restrict__ bias, float* __restrict__ out) {
    if (blockIdx.x == 0 && threadIdx.x < 3) {
        g_barcnt[threadIdx.x] = 0;
        g_barrel[threadIdx.x] = 0;
    }
    const int lane = threadIdx.x & 31;
    const int n = blockIdx.x * 8 + (threadIdx.x >> 5);
    if (n >= NN) return;

    const float ad = g_adst[n];
    const float2 bv = *(const float2*)(bias + lane * 2);

    // self loop
    float al = ad + g_asrc[n];
    al = (al > 0.f) ? al : 0.2f * al;
    float wself = __expf(al);
    float2 hv = *(const float2*)(g_h + n * OC + lane * 2);
    float wsum = wself;
    float a0 = wself * hv.x, a1 = wself * hv.y;

    const int beg = g_ptr[n];
    const int end = g_ptr[n + 1];
    for (int base = beg; base < end; base += 32) {
        const int idx = base + lane;
        int s = 0;
        float w = 0.f;
        if (idx < end) {
            s = g_col[idx];                         // coalesced
            float a = ad + g_asrc[s];
            a = (a > 0.f) ? a : 0.2f * a;
            w = __expf(a);
        }
        // chunk weight sum (allreduce)
        float wtot = w;
#pragma unroll
        for (int o = 16; o > 0; o >>= 1) wtot += __shfl_xor_sync(0xffffffffu, wtot, o);
        wsum += wtot;

        const int cnt = min(32, end - base);
        int j = 0;
        for (; j + 3 < cnt; j += 4) {
            int s0 = __shfl_sync(0xffffffffu, s, j);
            int s1 = __shfl_sync(0xffffffffu, s, j + 1);
            int s2 = __shfl_sync(0xffffffffu, s, j + 2);
            int s3 = __shfl_sync(0xffffffffu, s, j + 3);
            float w0 = __shfl_sync(0xffffffffu, w, j);
            float w1 = __shfl_sync(0xffffffffu, w, j + 1);
            float w2 = __shfl_sync(0xffffffffu, w, j + 2);
            float w3 = __shfl_sync(0xffffffffu, w, j + 3);
            float2 h0 = *(const float2*)(g_h + s0 * OC + lane * 2);
            float2 h1 = *(const float2*)(g_h + s1 * OC + lane * 2);
            float2 h2 = *(const float2*)(g_h + s2 * OC + lane * 2);
            float2 h3 = *(const float2*)(g_h + s3 * OC + lane * 2);
            a0 += w0 * h0.x; a1 += w0 * h0.y;
            a0 += w1 * h1.x; a1 += w1 * h1.y;
            a0 += w2 * h2.x; a1 += w2 * h2.y;
            a0 += w3 * h3.x; a1 += w3 * h3.y;
        }
        for (; j < cnt; j++) {
            int sj = __shfl_sync(0xffffffffu, s, j);
            float wj = __shfl_sync(0xffffffffu, w, j);
            float2 h2 = *(const float2*)(g_h + sj * OC + lane * 2);
            a0 += wj * h2.x; a1 += wj * h2.y;
        }
    }

    float inv_s = 1.0f / (wsum + 1e-16f);
    float v0 = a0 * inv_s + bv.x;
    float v1 = a1 * inv_s + bv.y;

    float ss = v0 * v0 + v1 * v1;
#pragma unroll
    for (int o = 16; o > 0; o >>= 1) ss += __shfl_xor_sync(0xffffffffu, ss, o);
    float inv = 1.0f / fmaxf(sqrtf(ss), 1e-12f);
    *(float2*)(out + n * OC + lane * 2) = make_float2(v0 * inv, v1 * inv);
}

extern "C" void kernel_launch(void* const* d_in, const int* in_sizes, int n_in,
                              void* d_out, int out_size) {
    const float* x = (const float*)d_in[0];
    const int* ei32 = (const int*)d_in[1];   // dtype sniffed on device
    const float* W = (const float*)d_in[2];
    const float* att = (const float*)d_in[3];
    const float* bias = (const float*)d_in[4];
    float* out = (float*)d_out;

    mega<<<GRID, 256>>>(x, W, att, ei32);
    k6_gather<<<(NN + 7) / 8, 256>>>(bias, out);
}